// round 7
// baseline (speedup 1.0000x reference)
#include <cuda_runtime.h>
#include <cuda_bf16.h>

#define BATCH 32
#define QN 16
#define CD 2048
#define PT 288
#define NPROT 2048
#define OFS (512 * 2048)
#define WSZ ((size_t)2048 * 2048)
#define SCALE_C 0.022097086912079608f  // 2048^-0.5

struct Ptr5 { const float* p[5]; };

// ----------------------------- scratch -------------------------------------
__device__ __align__(128) float g_xs   [(size_t)BATCH * PT * CD];
__device__ __align__(128) float g_invn [BATCH * PT];
__device__ __align__(128) float g_S    [BATCH * PT * PT];
__device__ __align__(128) float g_g2   [(size_t)BATCH * PT * CD];
__device__ __align__(128) float g_rq1  [QN * CD];
__device__ __align__(128) float g_qc1  [QN * CD];
__device__ __align__(128) float g_lg1  [BATCH * QN * PT];
__device__ __align__(128) float g_qln  [512 * CD];
__device__ __align__(128) float g_v    [BATCH * CD];
__device__ __align__(128) float g_mv2  [BATCH];
__device__ __align__(128) float g_u    [(size_t)NPROT * CD];
__device__ __align__(128) float g_su2  [NPROT];
__device__ __align__(128) float g_uv   [BATCH * NPROT];
__device__ __align__(128) float g_tmp512[512 * CD];
__device__ __align__(128) float g_rdq  [512 * CD];
__device__ __align__(128) float g_M    [512 * NPROT];
__device__ __align__(128) float g_t    [512];
__device__ __align__(128) float g_sumw [512];
__device__ __align__(128) float g_y    [512 * CD];
__device__ __align__(128) float g_fpro [512 * CD];
__device__ __align__(128) float g_qc2  [512 * CD];
__device__ __align__(128) float g_lg2  [BATCH * QN * PT];
__device__ __align__(128) float g_lg3  [BATCH * QN * 4 * PT];
__device__ __align__(128) float g_bias3[512 * 4];
__device__ __align__(128) float g_smw  [QN];
__device__ __align__(128) int   g_perm [BATCH];
__device__ __align__(128) int   g_omap [BATCH * 4];
__device__ __align__(128) long long g_offA3[128];
__device__ __align__(128) long long g_offB3[128];
__device__ __align__(128) long long g_offC3[128];
__device__ __align__(128) long long g_offA4[128];
__device__ __align__(128) long long g_offB4[128];
// input router
__device__ float g_acc[5];
__device__ int   g_wsel[5];
__device__ __align__(128) float g_wbuf[5 * WSZ];   // Wcq, Wcg, Wdq, Wdg, proto

// ----------------------------- helpers -------------------------------------
__device__ __forceinline__ float blockReduce(float v, bool domax) {
    __shared__ float sd[256];
    int t = threadIdx.x;
    __syncthreads();
    sd[t] = v;
    __syncthreads();
    for (int s = 128; s > 0; s >>= 1) {
        if (t < s) sd[t] = domax ? fmaxf(sd[t], sd[t + s]) : (sd[t] + sd[t + s]);
        __syncthreads();
    }
    return sd[0];
}

// ----------------------------- input router --------------------------------
__global__ void classify_zero() {
    if (threadIdx.x < 5) g_acc[threadIdx.x] = 0.f;
}

__global__ __launch_bounds__(256) void classify_sum(Ptr5 c) {
    int cand = blockIdx.y;
    const float* p = c.p[cand];
    float s = 0.f;
    for (size_t i = (size_t)blockIdx.x * 256 + threadIdx.x; i < WSZ;
         i += (size_t)gridDim.x * 256) {
        float v = p[i];
        s += v * v;
    }
    s = blockReduce(s, false);
    if (threadIdx.x == 0) atomicAdd(&g_acc[cand], s);
}

__global__ void classify_pick() {
    if (threadIdx.x != 0) return;
    int pi = 0;
    float best = g_acc[0];
    for (int i = 1; i < 5; i++)
        if (g_acc[i] < best) { best = g_acc[i]; pi = i; }
    // dest order: 0=Wcq 1=Wcg 2=Wdq 3=Wdg 4=proto
    if (pi == 4) {                    // alphabetical: Wcg,Wcq,Wdg,Wdq,proto
        g_wsel[0] = 1; g_wsel[1] = 0; g_wsel[2] = 3; g_wsel[3] = 2; g_wsel[4] = 4;
    } else {                          // dict order: proto at pi, W's in order
        int w[4], k = 0;
        for (int i = 0; i < 5; i++) if (i != pi) w[k++] = i;
        g_wsel[0] = w[0]; g_wsel[1] = w[1]; g_wsel[2] = w[2]; g_wsel[3] = w[3];
        g_wsel[4] = pi;
    }
}

__global__ __launch_bounds__(256) void router_copy(Ptr5 c) {
    int d = blockIdx.y;
    const float* src = c.p[g_wsel[d]];
    float* dst = g_wbuf + (size_t)d * WSZ;
    for (size_t i = ((size_t)blockIdx.x * 256 + threadIdx.x) * 4; i < WSZ;
         i += (size_t)gridDim.x * 1024) {
        float4 v = *reinterpret_cast<const float4*>(src + i);
        *reinterpret_cast<float4*>(dst + i) = v;
    }
}

// ----------------------------- simple GEMMs ---------------------------------
// NT: C[m,n] = sum_k A[m,k]*B[n,k]. warp-per-n, lane-strided k, shuffle reduce.
// grid: (N/8, M, Z), 256 threads. offsel: 0 = z-strides, 1 = lg3 tables.
__global__ __launch_bounds__(256)
void gemm_nt(const float* __restrict__ A, long long lda, long long sA,
             const float* __restrict__ B, long long ldb, long long sB,
             float* __restrict__ C, long long ldc, long long sC,
             int N, int K, int offsel)
{
    int z = blockIdx.z;
    const float* Ab; const float* Bb; float* Cb;
    if (offsel == 1) {
        Ab = A + g_offA3[z]; Bb = B + g_offB3[z]; Cb = C + g_offC3[z];
    } else {
        Ab = A + (long long)z * sA; Bb = B + (long long)z * sB;
        Cb = C + (long long)z * sC;
    }
    int m = blockIdx.y;
    int warp = threadIdx.x >> 5, lane = threadIdx.x & 31;
    int n = blockIdx.x * 8 + warp;
    if (n >= N) return;
    const float* Ar = Ab + (long long)m * lda;
    const float* Br = Bb + (long long)n * ldb;
    float s0 = 0.f, s1 = 0.f;
    int k = lane;
    for (; k + 32 < K; k += 64) {
        s0 += Ar[k] * Br[k];
        s1 += Ar[k + 32] * Br[k + 32];
    }
    if (k < K) s0 += Ar[k] * Br[k];
    float s = s0 + s1;
    for (int o = 16; o; o >>= 1) s += __shfl_down_sync(0xffffffffu, s, o);
    if (lane == 0) Cb[(long long)m * ldc + n] = s;
}

// NN: C[m,n] (+)= sum_k A[m,k]*B[k,n]. thread-per-n, scalar k loop.
// grid: (ceil(N/256), M, Z), 256 threads. offsel: 0 = z-strides, 2 = fcor tables.
__global__ __launch_bounds__(256)
void gemm_nn(const float* __restrict__ A, long long lda, long long sA,
             const float* __restrict__ B, long long ldb, long long sB,
             float* __restrict__ C, long long ldc, long long sC,
             int N, int K, int acc, int offsel, int zoff)
{
    int z = blockIdx.z;
    const float* Ab; const float* Bb; float* Cb;
    if (offsel == 2) {
        Ab = A + g_offA4[z + zoff]; Bb = B + g_offB4[z + zoff];
        Cb = C + (long long)z * sC;
    } else {
        Ab = A + (long long)z * sA; Bb = B + (long long)z * sB;
        Cb = C + (long long)z * sC;
    }
    int m = blockIdx.y;
    int n = blockIdx.x * 256 + threadIdx.x;
    if (n >= N) return;
    const float* Ar = Ab + (long long)m * lda;
    float a0 = 0.f, a1 = 0.f;
    int k = 0;
    for (; k + 2 <= K; k += 2) {
        a0 += Ar[k] * Bb[(long long)k * ldb + n];
        a1 += Ar[k + 1] * Bb[(long long)(k + 1) * ldb + n];
    }
    if (k < K) a0 += Ar[k] * Bb[(long long)k * ldb + n];
    float s = a0 + a1;
    long long ci = (long long)m * ldc + n;
    if (acc) Cb[ci] += s; else Cb[ci] = s;
}

// ----------------------------- small kernels --------------------------------
__global__ void setup_kernel(const unsigned int* __restrict__ sub32,
                             const float* __restrict__ weights)
{
    __shared__ int sub[BATCH];
    int t = threadIdx.x;
    if (t == 0) {
        bool isF = true, isI = true;
        for (int i = 0; i < BATCH; i++) {
            unsigned v = sub32[i];
            if (!(v == 0u || v == 0x3F800000u)) isF = false;
            if (!(v == 0u || v == 1u))          isI = false;
        }
        const unsigned char* b8 = (const unsigned char*)sub32;
        for (int i = 0; i < BATCH; i++)
            sub[i] = isF ? (sub32[i] != 0u) : (isI ? (int)sub32[i] : (b8[i] != 0));
        int idx = 0;
        for (int pass = 0; pass < 2; pass++)
            for (int i = 0; i < BATCH; i++)
                if (sub[i] == pass) g_perm[idx++] = i;
        float mx = -1e30f;
        for (int q = 0; q < QN; q++) mx = fmaxf(mx, weights[q]);
        float s = 0.f;
        for (int q = 0; q < QN; q++) s += expf(weights[q] - mx);
        for (int q = 0; q < QN; q++) g_smw[q] = expf(weights[q] - mx) / s;
    }
    __syncthreads();
    if (t < 128) {
        int b = t >> 2, j = t & 3;
        int o = (g_perm[b] / 4) * 4 + j;
        g_omap[t]  = o;
        g_offA3[t] = (long long)b * QN * CD;
        g_offB3[t] = (long long)o * PT * CD;
        g_offC3[t] = (long long)b * QN * (4 * PT) + (long long)j * PT;
        int j2 = t >> 5, b2 = t & 31;
        int o2 = (g_perm[b2] / 4) * 4 + j2;
        g_offA4[t] = (long long)b2 * QN * (4 * PT) + (long long)j2 * PT;
        g_offB4[t] = (long long)o2 * PT * CD;
    }
}

// x[b,c,p] -> xs[b,p,c], 32x32 smem tiles
__global__ void transpose_kernel(const float* __restrict__ x)
{
    __shared__ float tile[32][33];
    int b = blockIdx.z;
    int c0 = blockIdx.x * 32, p0 = blockIdx.y * 32;
    int tx = threadIdx.x, ty = threadIdx.y;   // 32 x 8
    const float* xb = x + (size_t)b * CD * PT;
    for (int j = 0; j < 32; j += 8)
        tile[ty + j][tx] = xb[(size_t)(c0 + ty + j) * PT + p0 + tx];
    __syncthreads();
    float* xsb = g_xs + (size_t)b * PT * CD;
    for (int j = 0; j < 32; j += 8)
        xsb[(size_t)(p0 + ty + j) * CD + c0 + tx] = tile[tx][ty + j];
}

// inverse L2 norm per token row of xs
__global__ __launch_bounds__(256) void colnorm_kernel()
{
    int row = blockIdx.x;                 // b*PT+p
    const float* r = g_xs + (size_t)row * CD;
    int tid = threadIdx.x;
    float s = 0.f;
    for (int c = tid; c < CD; c += 256) { float v = r[c]; s += v * v; }
    s = blockReduce(s, false);
    if (tid == 0) g_invn[row] = 1.f / fmaxf(sqrtf(s), 1e-12f);
}

__global__ __launch_bounds__(256) void softmaxS_kernel()
{
    int row = blockIdx.x;
    int b = row / PT, p = row % PT;
    float* Sr = g_S + (size_t)row * PT;
    float ip = g_invn[b * PT + p];
    const float* iv = g_invn + b * PT;
    int tid = threadIdx.x;
    float mx = -1e30f;
    for (int q = tid; q < PT; q += 256) mx = fmaxf(mx, Sr[q] * ip * iv[q]);
    mx = blockReduce(mx, true);
    float sum = 0.f;
    for (int q = tid; q < PT; q += 256) {
        float e = expf(Sr[q] * ip * iv[q] - mx);
        Sr[q] = e; sum += e;
    }
    sum = blockReduce(sum, false);
    float inv = 1.f / sum;
    for (int q = tid; q < PT; q += 256) Sr[q] *= inv;
}

__global__ __launch_bounds__(256)
void catcher_softmax_kernel(float* __restrict__ lg, int L, int useBias)
{
    int row = blockIdx.x, tid = threadIdx.x;
    float* p = lg + (size_t)row * L;
    float mx = -1e30f;
    for (int k = tid; k < L; k += 256) {
        float v = p[k];
        if (useBias) v += g_bias3[row * 4 + k / PT];
        mx = fmaxf(mx, v * SCALE_C);
    }
    mx = blockReduce(mx, true);
    float sum = 0.f;
    for (int k = tid; k < L; k += 256) {
        float v = p[k];
        if (useBias) v += g_bias3[row * 4 + k / PT];
        float e = expf(v * SCALE_C - mx);
        p[k] = e; sum += e;
    }
    sum = blockReduce(sum, false);
    float inv = 1.f / sum;
    for (int k = tid; k < L; k += 256) p[k] *= inv;
}

__global__ __launch_bounds__(256) void stats1_kernel(const float* __restrict__ frel)
{
    int b = blockIdx.x, tid = threadIdx.x;
    float part = 0.f;
    for (int c = tid; c < CD; c += 256) {
        float s = 0.f;
        for (int q = 0; q < QN; q++) s += frel[((size_t)b * QN + q) * CD + c];
        s *= (1.f / QN);
        g_v[b * CD + c] = s;
        part += s;
    }
    float mbm = blockReduce(part, false) * (1.f / CD);
    float p2 = 0.f;
    for (int c = tid; c < CD; c += 256) {
        float vv = g_v[b * CD + c] - mbm;
        g_v[b * CD + c] = vv;
        p2 += vv * vv;
    }
    float mv = blockReduce(p2, false) * (1.f / CD);
    if (tid == 0) g_mv2[b] = mv;
}

__global__ __launch_bounds__(256) void ln_kernel(const float* __restrict__ frel)
{
    int row = blockIdx.x, tid = threadIdx.x;
    const float* p = frel + (size_t)row * CD;
    float s = 0.f;
    for (int c = tid; c < CD; c += 256) s += p[c];
    float m = blockReduce(s, false) * (1.f / CD);
    float v = 0.f;
    for (int c = tid; c < CD; c += 256) { float d = p[c] - m; v += d * d; }
    float var = blockReduce(v, false) * (1.f / CD);
    float rs = rsqrtf(var + 1e-5f);
    for (int c = tid; c < CD; c += 256) g_qln[(size_t)row * CD + c] = (p[c] - m) * rs;
}

__global__ __launch_bounds__(256) void protoprep_kernel(const float* __restrict__ proto)
{
    int n = blockIdx.x, tid = threadIdx.x;
    const float* p = proto + (size_t)n * CD;
    float s = 0.f;
    for (int c = tid; c < CD; c += 256) s += p[c];
    float m = blockReduce(s, false) * (1.f / CD);
    float ss = 0.f;
    for (int c = tid; c < CD; c += 256) {
        float uu = p[c] - m;
        g_u[(size_t)n * CD + c] = uu;
        ss += uu * uu;
    }
    float su = blockReduce(ss, false) * (1.f / CD);
    if (tid == 0) g_su2[n] = su;
}

__global__ __launch_bounds__(256) void tdot_kernel()
{
    int row = blockIdx.x, b = row >> 4, tid = threadIdx.x;
    float s = 0.f;
    for (int c = tid; c < CD; c += 256)
        s += g_rdq[(size_t)row * CD + c] * g_v[b * CD + c];
    s = blockReduce(s, false);
    if (tid == 0) g_t[row] = s;
}

__global__ __launch_bounds__(256) void dsoftmax_kernel()
{
    int row = blockIdx.x, b = row >> 4, tid = threadIdx.x;
    float lg[8], sv[8];
    float tval = g_t[row];
    float mvb = g_mv2[b];
    float mx = -1e30f;
#pragma unroll
    for (int i = 0; i < 8; i++) {
        int n = tid + i * 256;
        float s2 = g_su2[n] - (2.f / CD) * g_uv[b * NPROT + n] + mvb + 1e-5f;
        float s = sqrtf(fmaxf(s2, 1e-20f));
        sv[i] = s;
        float v = SCALE_C * (g_M[(size_t)row * NPROT + n] - tval) / s;
        lg[i] = v;
        mx = fmaxf(mx, v);
    }
    mx = blockReduce(mx, true);
    float sum = 0.f;
#pragma unroll
    for (int i = 0; i < 8; i++) { float e = expf(lg[i] - mx); lg[i] = e; sum += e; }
    sum = blockReduce(sum, false);
    float inv = 1.f / sum;
    float ws = 0.f;
#pragma unroll
    for (int i = 0; i < 8; i++) {
        float w = lg[i] * inv / sv[i];
        g_M[(size_t)row * NPROT + tid + i * 256] = w;
        ws += w;
    }
    ws = blockReduce(ws, false);
    if (tid == 0) g_sumw[row] = ws;
}

__global__ __launch_bounds__(256)
void fpro_kernel(const float* __restrict__ frel, float* __restrict__ out_fpro)
{
    int row = blockIdx.x, b = row >> 4, q = row & 15, tid = threadIdx.x;
    float sw = g_sumw[row], smw = g_smw[q];
    for (int c = tid; c < CD; c += 256) {
        float val = frel[(size_t)row * CD + c] + g_y[(size_t)row * CD + c]
                  - sw * g_v[b * CD + c];
        g_fpro[(size_t)row * CD + c] = val;
        out_fpro[(size_t)row * CD + c] = val * smw;
    }
}

__global__ __launch_bounds__(256)
void bias3_kernel(const int* __restrict__ cam_ids, const float* __restrict__ cam_table)
{
    int z = blockIdx.x;
    int row = z >> 2, j = z & 3, b = row >> 4, tid = threadIdx.x;
    int inst = g_omap[b * 4 + j];
    int cr = cam_ids[inst] - 1;
    cr = max(0, min(5, cr));
    float s = 0.f;
    for (int c = tid; c < CD; c += 256)
        s += g_qc2[(size_t)row * CD + c] * cam_table[(size_t)cr * CD + c];
    s = blockReduce(s, false);
    if (tid == 0) g_bias3[z] = s;
}

// ----------------------------- launch --------------------------------------
extern "C" void kernel_launch(void* const* d_in, const int* in_sizes, int n_in,
                              void* d_out, int out_size)
{
    // ---- order-agnostic input binding by element count ----
    const float* x = nullptr;
    const float* query_v = nullptr;
    const float* weights = nullptr;
    const float* cam_tab = nullptr;
    const int*   cam_ids = nullptr;
    const unsigned int* sub = nullptr;
    Ptr5 big; int nbig = 0, n32 = 0;
    for (int i = 0; i < n_in; i++) {
        switch (in_sizes[i]) {
            case 18874368: x = (const float*)d_in[i]; break;
            case 32768:    query_v = (const float*)d_in[i]; break;
            case 16:       weights = (const float*)d_in[i]; break;
            case 12288:    cam_tab = (const float*)d_in[i]; break;
            case 589824:   /* pos_embed unused */ break;
            case 4194304:  if (nbig < 5) big.p[nbig++] = (const float*)d_in[i]; break;
            case 32:
                if (n32 == 0) cam_ids = (const int*)d_in[i];
                else          sub     = (const unsigned int*)d_in[i];
                n32++;
                break;
            default: break;
        }
    }

    // ---- DEVICE addresses of all scratch symbols (the R4-R6 bug: passing
    // __device__ symbols as kernel args from host passes the host shadow,
    // which GB300 ATS silently dereferences as host memory) ----
    float *xs, *S, *g2, *rq1, *qc1, *lg1, *qln, *v, *u, *uv;
    float *tmp512, *rdq, *M, *y, *fpro, *qc2, *lg2, *lg3, *wb;
    cudaGetSymbolAddress((void**)&xs,    g_xs);
    cudaGetSymbolAddress((void**)&S,     g_S);
    cudaGetSymbolAddress((void**)&g2,    g_g2);
    cudaGetSymbolAddress((void**)&rq1,   g_rq1);
    cudaGetSymbolAddress((void**)&qc1,   g_qc1);
    cudaGetSymbolAddress((void**)&lg1,   g_lg1);
    cudaGetSymbolAddress((void**)&qln,   g_qln);
    cudaGetSymbolAddress((void**)&v,     g_v);
    cudaGetSymbolAddress((void**)&u,     g_u);
    cudaGetSymbolAddress((void**)&uv,    g_uv);
    cudaGetSymbolAddress((void**)&tmp512,g_tmp512);
    cudaGetSymbolAddress((void**)&rdq,   g_rdq);
    cudaGetSymbolAddress((void**)&M,     g_M);
    cudaGetSymbolAddress((void**)&y,     g_y);
    cudaGetSymbolAddress((void**)&fpro,  g_fpro);
    cudaGetSymbolAddress((void**)&qc2,   g_qc2);
    cudaGetSymbolAddress((void**)&lg2,   g_lg2);
    cudaGetSymbolAddress((void**)&lg3,   g_lg3);
    cudaGetSymbolAddress((void**)&wb,    g_wbuf);
    const float* Wcq  = wb;
    const float* Wcg  = wb + WSZ;
    const float* Wdq  = wb + 2 * WSZ;
    const float* Wdg  = wb + 3 * WSZ;
    const float* proto = wb + 4 * WSZ;

    float* out = (float*)d_out;
    float* f_rel = out;
    float* f_pro = out + OFS;
    float* f_rec = out + 2 * OFS;
    float* f_cor = out + 3 * OFS;

    // ---- classify the five 4M tensors, route into fixed slots ----
    classify_zero<<<1, 32>>>();
    classify_sum<<<dim3(256, 5), 256>>>(big);
    classify_pick<<<1, 32>>>();
    router_copy<<<dim3(512, 5), 256>>>(big);

    setup_kernel<<<1, 128>>>(sub, weights);
    transpose_kernel<<<dim3(64, 9, 32), dim3(32, 8)>>>(x);
    colnorm_kernel<<<BATCH * PT, 256>>>();

    // gram S[p,q] = xs[p]·xs[q]
    gemm_nt<<<dim3(36, PT, BATCH), 256>>>(xs, CD, (long long)PT * CD,
        xs, CD, (long long)PT * CD, S, PT, (long long)PT * PT, PT, CD, 0);
    softmaxS_kernel<<<BATCH * PT, 256>>>();
    // g2 = S @ xs
    gemm_nn<<<dim3(8, PT, BATCH), 256>>>(S, PT, (long long)PT * PT,
        xs, CD, (long long)PT * CD, g2, CD, (long long)PT * CD,
        CD, PT, 0, 0, 0);

    // rq1 = query @ Wcq^T ; qc1 = rq1 @ Wcg
    gemm_nt<<<dim3(256, QN, 1), 256>>>(query_v, CD, 0, Wcq, CD, 0,
        rq1, CD, 0, CD, CD, 0);
    gemm_nn<<<dim3(8, QN, 1), 256>>>(rq1, CD, 0, Wcg, CD, 0,
        qc1, CD, 0, CD, CD, 0, 0, 0);
    // lg1[b,q,n] = qc1[q]·g2[b,n]
    gemm_nt<<<dim3(36, QN, BATCH), 256>>>(qc1, CD, 0,
        g2, CD, (long long)PT * CD, lg1, PT, (long long)QN * PT, PT, CD, 0);
    catcher_softmax_kernel<<<512, 256>>>(lg1, PT, 0);
    // f_rel = att1 @ g2
    gemm_nn<<<dim3(8, QN, BATCH), 256>>>(lg1, PT, (long long)QN * PT,
        g2, CD, (long long)PT * CD, f_rel, CD, (long long)QN * CD,
        CD, PT, 0, 0, 0);

    // ---- deltaor (LN factorized) ----
    stats1_kernel<<<BATCH, 256>>>(f_rel);
    ln_kernel<<<512, 256>>>(f_rel);
    protoprep_kernel<<<NPROT, 256>>>(proto);
    gemm_nt<<<dim3(256, 512, 1), 256>>>(qln, CD, 0, Wdq, CD, 0,
        tmp512, CD, 0, CD, CD, 0);
    gemm_nn<<<dim3(8, 512, 1), 256>>>(tmp512, CD, 0, Wdg, CD, 0,
        rdq, CD, 0, CD, CD, 0, 0, 0);
    gemm_nt<<<dim3(256, BATCH, 1), 256>>>(v, CD, 0, u, CD, 0,
        uv, NPROT, 0, NPROT, CD, 0);
    gemm_nt<<<dim3(256, 512, 1), 256>>>(rdq, CD, 0, u, CD, 0,
        M, NPROT, 0, NPROT, CD, 0);
    tdot_kernel<<<512, 256>>>();
    dsoftmax_kernel<<<512, 256>>>();
    gemm_nn<<<dim3(8, 512, 1), 256>>>(M, NPROT, 0, u, CD, 0,
        y, CD, 0, CD, NPROT, 0, 0, 0);
    fpro_kernel<<<512, 256>>>(f_rel, f_pro);

    // ---- shared projection of raw f_pro ----
    gemm_nt<<<dim3(256, 512, 1), 256>>>(fpro, CD, 0, Wcq, CD, 0,
        tmp512, CD, 0, CD, CD, 0);
    gemm_nn<<<dim3(8, 512, 1), 256>>>(tmp512, CD, 0, Wcg, CD, 0,
        qc2, CD, 0, CD, CD, 0, 0, 0);

    // f_rec
    gemm_nt<<<dim3(36, QN, BATCH), 256>>>(qc2, CD, (long long)QN * CD,
        g2, CD, (long long)PT * CD, lg2, PT, (long long)QN * PT, PT, CD, 0);
    catcher_softmax_kernel<<<512, 256>>>(lg2, PT, 0);
    gemm_nn<<<dim3(8, QN, BATCH), 256>>>(lg2, PT, (long long)QN * PT,
        g2, CD, (long long)PT * CD, f_rec, CD, (long long)QN * CD,
        CD, PT, 0, 0, 0);

    // f_cor: 128 gathered blocks (offset tables), per-block cam bias
    gemm_nt<<<dim3(36, QN, 128), 256>>>(qc2, CD, 0,
        g2, CD, 0, lg3, 4 * PT, 0, PT, CD, 1);
    bias3_kernel<<<2048, 256>>>(cam_ids, cam_tab);
    catcher_softmax_kernel<<<512, 256>>>(lg3, 4 * PT, 1);
    for (int j = 0; j < 4; j++) {
        gemm_nn<<<dim3(8, QN, BATCH), 256>>>(lg3, 4 * PT, 0,
            g2, CD, 0, f_cor, CD, (long long)QN * CD,
            CD, PT, (j > 0) ? 1 : 0, 2, j * 32);
    }
}

// round 8
// speedup vs baseline: 2.8518x; 2.8518x over previous
#include <cuda_runtime.h>
#include <cuda_bf16.h>

#define BATCH 32
#define QN 16
#define CD 2048
#define PT 288
#define NPROT 2048
#define OFS (512 * 2048)
#define WSZ ((size_t)2048 * 2048)
#define SCALE_C 0.022097086912079608f  // 2048^-0.5

struct Ptr5 { const float* p[5]; };

// ----------------------------- scratch -------------------------------------
__device__ __align__(128) float g_xs   [(size_t)BATCH * PT * CD];
__device__ __align__(128) float g_invn [BATCH * PT];
__device__ __align__(128) float g_S    [BATCH * PT * PT];
__device__ __align__(128) float g_g2   [(size_t)BATCH * PT * CD];
__device__ __align__(128) float g_rq1  [QN * CD];
__device__ __align__(128) float g_qc1  [QN * CD];
__device__ __align__(128) float g_lg1  [BATCH * QN * PT];
__device__ __align__(128) float g_qln  [512 * CD];
__device__ __align__(128) float g_v    [BATCH * CD];
__device__ __align__(128) float g_mv2  [BATCH];
__device__ __align__(128) float g_u    [(size_t)NPROT * CD];
__device__ __align__(128) float g_su2  [NPROT];
__device__ __align__(128) float g_uv   [BATCH * NPROT];
__device__ __align__(128) float g_tmp512[512 * CD];
__device__ __align__(128) float g_rdq  [512 * CD];
__device__ __align__(128) float g_M    [512 * NPROT];
__device__ __align__(128) float g_t    [512];
__device__ __align__(128) float g_sumw [512];
__device__ __align__(128) float g_y    [512 * CD];
__device__ __align__(128) float g_fpro [512 * CD];
__device__ __align__(128) float g_qc2  [512 * CD];
__device__ __align__(128) float g_lg2  [BATCH * QN * PT];
__device__ __align__(128) float g_lg3  [BATCH * QN * 4 * PT];
__device__ __align__(128) float g_bias3[512 * 4];
__device__ __align__(128) float g_smw  [QN];
__device__ __align__(128) int   g_perm [BATCH];
__device__ __align__(128) int   g_omap [BATCH * 4];
__device__ __align__(128) long long g_offA3[128];
__device__ __align__(128) long long g_offB3[128];
__device__ __align__(128) long long g_offC3[128];
__device__ __align__(128) long long g_offA4[128];
__device__ __align__(128) long long g_offB4[128];
// input router
__device__ float g_acc[5];
__device__ int   g_wsel[5];
__device__ __align__(128) float g_wbuf[5 * WSZ];   // Wcq, Wcg, Wdq, Wdg, proto

// ----------------------------- helpers -------------------------------------
__device__ __forceinline__ float blockReduce(float v, bool domax) {
    __shared__ float sd[256];
    int t = threadIdx.x;
    __syncthreads();
    sd[t] = v;
    __syncthreads();
    for (int s = 128; s > 0; s >>= 1) {
        if (t < s) sd[t] = domax ? fmaxf(sd[t], sd[t + s]) : (sd[t] + sd[t + s]);
        __syncthreads();
    }
    return sd[0];
}

// ----------------------------- input router --------------------------------
__global__ void classify_zero() {
    if (threadIdx.x < 5) g_acc[threadIdx.x] = 0.f;
}

__global__ __launch_bounds__(256) void classify_sum(Ptr5 c) {
    int cand = blockIdx.y;
    const float* p = c.p[cand];
    float s = 0.f;
    for (size_t i = (size_t)blockIdx.x * 256 + threadIdx.x; i < WSZ;
         i += (size_t)gridDim.x * 256) {
        float v = p[i];
        s += v * v;
    }
    s = blockReduce(s, false);
    if (threadIdx.x == 0) atomicAdd(&g_acc[cand], s);
}

__global__ void classify_pick() {
    if (threadIdx.x != 0) return;
    int pi = 0;
    float best = g_acc[0];
    for (int i = 1; i < 5; i++)
        if (g_acc[i] < best) { best = g_acc[i]; pi = i; }
    // dest order: 0=Wcq 1=Wcg 2=Wdq 3=Wdg 4=proto
    if (pi == 4) {                    // alphabetical: Wcg,Wcq,Wdg,Wdq,proto
        g_wsel[0] = 1; g_wsel[1] = 0; g_wsel[2] = 3; g_wsel[3] = 2; g_wsel[4] = 4;
    } else {                          // dict order: proto at pi, W's in order
        int w[4], k = 0;
        for (int i = 0; i < 5; i++) if (i != pi) w[k++] = i;
        g_wsel[0] = w[0]; g_wsel[1] = w[1]; g_wsel[2] = w[2]; g_wsel[3] = w[3];
        g_wsel[4] = pi;
    }
}

__global__ __launch_bounds__(256) void router_copy(Ptr5 c) {
    int d = blockIdx.y;
    const float* src = c.p[g_wsel[d]];
    float* dst = g_wbuf + (size_t)d * WSZ;
    for (size_t i = ((size_t)blockIdx.x * 256 + threadIdx.x) * 4; i < WSZ;
         i += (size_t)gridDim.x * 1024) {
        float4 v = *reinterpret_cast<const float4*>(src + i);
        *reinterpret_cast<float4*>(dst + i) = v;
    }
}

// ----------------------------- tiled GEMM -----------------------------------
// MODE 0: NT  C[m,n]=sum_k A[m,k]*B[n,k]
// MODE 1: NN  C[m,n]=sum_k A[m,k]*B[k,n]
// Tile: BM x 64, 256 threads. BM=64 -> 4x4/thread, BM=16 -> 1x4/thread.
// K % 16 == 0, N % 4 == 0, all lds/pointers 16B-aligned at float4 use sites.
// offsel: 0 = z strides, 1 = lg3 tables (A3/B3/C3), 2 = f_cor tables (A4/B4).
template <int MODE, int BM>
__global__ __launch_bounds__(256)
void gemm_t(const float* __restrict__ A, long long lda, long long sA,
            const float* __restrict__ B, long long ldb, long long sB,
            float* __restrict__ C, long long ldc, long long sC,
            int M, int N, int K, int acc, int offsel, int zoff)
{
    const int z = blockIdx.z;
    const float* Ab; const float* Bb; float* Cb;
    if (offsel == 1) {
        Ab = A + g_offA3[z]; Bb = B + g_offB3[z]; Cb = C + g_offC3[z];
    } else if (offsel == 2) {
        Ab = A + g_offA4[z + zoff]; Bb = B + g_offB4[z + zoff];
        Cb = C + (long long)z * sC;
    } else {
        Ab = A + (long long)z * sA; Bb = B + (long long)z * sB;
        Cb = C + (long long)z * sC;
    }
    const int m0 = blockIdx.y * BM, n0 = blockIdx.x * 64;
    constexpr int R = BM / 16;              // rows per thread (4 or 1)
    __shared__ float As[16][(BM == 64) ? 68 : 20];
    __shared__ float Bs[16][68];
    const int tid = threadIdx.x;
    const int tx = tid & 15, ty = tid >> 4;
    float accr[R][4];
#pragma unroll
    for (int i = 0; i < R; i++)
#pragma unroll
        for (int j = 0; j < 4; j++) accr[i][j] = 0.f;

    for (int k0 = 0; k0 < K; k0 += 16) {
        // ---- A tile (A is always [M,K] row-major) ----
        if (BM == 64) {
            int r = tid >> 2, kq = (tid & 3) << 2;
            float4 av = make_float4(0.f, 0.f, 0.f, 0.f);
            if (m0 + r < M)
                av = *reinterpret_cast<const float4*>(Ab + (long long)(m0 + r) * lda + k0 + kq);
            As[kq + 0][r] = av.x; As[kq + 1][r] = av.y;
            As[kq + 2][r] = av.z; As[kq + 3][r] = av.w;
        } else {
            int kx = tid & 15, my = tid >> 4;   // 16x16 scalar
            float av = 0.f;
            if (m0 + my < M)
                av = Ab[(long long)(m0 + my) * lda + k0 + kx];
            As[kx][my] = av;
        }
        // ---- B tile ----
        if (MODE == 0) {                        // B[N,K]
            int r = tid >> 2, kq = (tid & 3) << 2;
            float4 bv = make_float4(0.f, 0.f, 0.f, 0.f);
            if (n0 + r < N)
                bv = *reinterpret_cast<const float4*>(Bb + (long long)(n0 + r) * ldb + k0 + kq);
            Bs[kq + 0][r] = bv.x; Bs[kq + 1][r] = bv.y;
            Bs[kq + 2][r] = bv.z; Bs[kq + 3][r] = bv.w;
        } else {                                // B[K,N]
            int kk = tid >> 4, nq = (tid & 15) << 2;
            float4 bv = make_float4(0.f, 0.f, 0.f, 0.f);
            if (n0 + nq < N)
                bv = *reinterpret_cast<const float4*>(Bb + (long long)(k0 + kk) * ldb + n0 + nq);
            Bs[kk][nq + 0] = bv.x; Bs[kk][nq + 1] = bv.y;
            Bs[kk][nq + 2] = bv.z; Bs[kk][nq + 3] = bv.w;
        }
        __syncthreads();
#pragma unroll
        for (int kk = 0; kk < 16; kk++) {
            float4 bv = *reinterpret_cast<const float4*>(&Bs[kk][tx * 4]);
            if (BM == 64) {
                float4 av = *reinterpret_cast<const float4*>(&As[kk][ty * 4]);
                float a[4] = {av.x, av.y, av.z, av.w};
#pragma unroll
                for (int i = 0; i < 4; i++) {
                    accr[i][0] += a[i] * bv.x;
                    accr[i][1] += a[i] * bv.y;
                    accr[i][2] += a[i] * bv.z;
                    accr[i][3] += a[i] * bv.w;
                }
            } else {
                float a = As[kk][ty];
                accr[0][0] += a * bv.x;
                accr[0][1] += a * bv.y;
                accr[0][2] += a * bv.z;
                accr[0][3] += a * bv.w;
            }
        }
        __syncthreads();
    }
#pragma unroll
    for (int i = 0; i < R; i++) {
        int m = m0 + ty * R + i;
        if (m >= M) continue;
#pragma unroll
        for (int j = 0; j < 4; j++) {
            int n = n0 + tx * 4 + j;
            if (n < N) {
                long long ci = (long long)m * ldc + n;
                if (acc) Cb[ci] += accr[i][j];
                else     Cb[ci]  = accr[i][j];
            }
        }
    }
}

// ----------------------------- small kernels --------------------------------
__global__ void setup_kernel(const unsigned int* __restrict__ sub32,
                             const float* __restrict__ weights)
{
    __shared__ int sub[BATCH];
    int t = threadIdx.x;
    if (t == 0) {
        bool isF = true, isI = true;
        for (int i = 0; i < BATCH; i++) {
            unsigned v = sub32[i];
            if (!(v == 0u || v == 0x3F800000u)) isF = false;
            if (!(v == 0u || v == 1u))          isI = false;
        }
        const unsigned char* b8 = (const unsigned char*)sub32;
        for (int i = 0; i < BATCH; i++)
            sub[i] = isF ? (sub32[i] != 0u) : (isI ? (int)sub32[i] : (b8[i] != 0));
        int idx = 0;
        for (int pass = 0; pass < 2; pass++)
            for (int i = 0; i < BATCH; i++)
                if (sub[i] == pass) g_perm[idx++] = i;
        float mx = -1e30f;
        for (int q = 0; q < QN; q++) mx = fmaxf(mx, weights[q]);
        float s = 0.f;
        for (int q = 0; q < QN; q++) s += expf(weights[q] - mx);
        for (int q = 0; q < QN; q++) g_smw[q] = expf(weights[q] - mx) / s;
    }
    __syncthreads();
    if (t < 128) {
        int b = t >> 2, j = t & 3;
        int o = (g_perm[b] / 4) * 4 + j;
        g_omap[t]  = o;
        g_offA3[t] = (long long)b * QN * CD;
        g_offB3[t] = (long long)o * PT * CD;
        g_offC3[t] = (long long)b * QN * (4 * PT) + (long long)j * PT;
        int j2 = t >> 5, b2 = t & 31;
        int o2 = (g_perm[b2] / 4) * 4 + j2;
        g_offA4[t] = (long long)b2 * QN * (4 * PT) + (long long)j2 * PT;
        g_offB4[t] = (long long)o2 * PT * CD;
    }
}

// x[b,c,p] -> xs[b,p,c], 32x32 smem tiles
__global__ void transpose_kernel(const float* __restrict__ x)
{
    __shared__ float tile[32][33];
    int b = blockIdx.z;
    int c0 = blockIdx.x * 32, p0 = blockIdx.y * 32;
    int tx = threadIdx.x, ty = threadIdx.y;   // 32 x 8
    const float* xb = x + (size_t)b * CD * PT;
    for (int j = 0; j < 32; j += 8)
        tile[ty + j][tx] = xb[(size_t)(c0 + ty + j) * PT + p0 + tx];
    __syncthreads();
    float* xsb = g_xs + (size_t)b * PT * CD;
    for (int j = 0; j < 32; j += 8)
        xsb[(size_t)(p0 + ty + j) * CD + c0 + tx] = tile[tx][ty + j];
}

// inverse L2 norm per token row of xs
__global__ __launch_bounds__(256) void colnorm_kernel()
{
    int row = blockIdx.x;                 // b*PT+p
    const float* r = g_xs + (size_t)row * CD;
    int tid = threadIdx.x;
    float s = 0.f;
    for (int c = tid; c < CD; c += 256) { float v = r[c]; s += v * v; }
    s = blockReduce(s, false);
    if (tid == 0) g_invn[row] = 1.f / fmaxf(sqrtf(s), 1e-12f);
}

__global__ __launch_bounds__(256) void softmaxS_kernel()
{
    int row = blockIdx.x;
    int b = row / PT, p = row % PT;
    float* Sr = g_S + (size_t)row * PT;
    float ip = g_invn[b * PT + p];
    const float* iv = g_invn + b * PT;
    int tid = threadIdx.x;
    float mx = -1e30f;
    for (int q = tid; q < PT; q += 256) mx = fmaxf(mx, Sr[q] * ip * iv[q]);
    mx = blockReduce(mx, true);
    float sum = 0.f;
    for (int q = tid; q < PT; q += 256) {
        float e = expf(Sr[q] * ip * iv[q] - mx);
        Sr[q] = e; sum += e;
    }
    sum = blockReduce(sum, false);
    float inv = 1.f / sum;
    for (int q = tid; q < PT; q += 256) Sr[q] *= inv;
}

__global__ __launch_bounds__(256)
void catcher_softmax_kernel(float* __restrict__ lg, int L, int useBias)
{
    int row = blockIdx.x, tid = threadIdx.x;
    float* p = lg + (size_t)row * L;
    float mx = -1e30f;
    for (int k = tid; k < L; k += 256) {
        float v = p[k];
        if (useBias) v += g_bias3[row * 4 + k / PT];
        mx = fmaxf(mx, v * SCALE_C);
    }
    mx = blockReduce(mx, true);
    float sum = 0.f;
    for (int k = tid; k < L; k += 256) {
        float v = p[k];
        if (useBias) v += g_bias3[row * 4 + k / PT];
        float e = expf(v * SCALE_C - mx);
        p[k] = e; sum += e;
    }
    sum = blockReduce(sum, false);
    float inv = 1.f / sum;
    for (int k = tid; k < L; k += 256) p[k] *= inv;
}

__global__ __launch_bounds__(256) void stats1_kernel(const float* __restrict__ frel)
{
    int b = blockIdx.x, tid = threadIdx.x;
    float part = 0.f;
    for (int c = tid; c < CD; c += 256) {
        float s = 0.f;
        for (int q = 0; q < QN; q++) s += frel[((size_t)b * QN + q) * CD + c];
        s *= (1.f / QN);
        g_v[b * CD + c] = s;
        part += s;
    }
    float mbm = blockReduce(part, false) * (1.f / CD);
    float p2 = 0.f;
    for (int c = tid; c < CD; c += 256) {
        float vv = g_v[b * CD + c] - mbm;
        g_v[b * CD + c] = vv;
        p2 += vv * vv;
    }
    float mv = blockReduce(p2, false) * (1.f / CD);
    if (tid == 0) g_mv2[b] = mv;
}

__global__ __launch_bounds__(256) void ln_kernel(const float* __restrict__ frel)
{
    int row = blockIdx.x, tid = threadIdx.x;
    const float* p = frel + (size_t)row * CD;
    float s = 0.f;
    for (int c = tid; c < CD; c += 256) s += p[c];
    float m = blockReduce(s, false) * (1.f / CD);
    float v = 0.f;
    for (int c = tid; c < CD; c += 256) { float d = p[c] - m; v += d * d; }
    float var = blockReduce(v, false) * (1.f / CD);
    float rs = rsqrtf(var + 1e-5f);
    for (int c = tid; c < CD; c += 256) g_qln[(size_t)row * CD + c] = (p[c] - m) * rs;
}

__global__ __launch_bounds__(256) void protoprep_kernel(const float* __restrict__ proto)
{
    int n = blockIdx.x, tid = threadIdx.x;
    const float* p = proto + (size_t)n * CD;
    float s = 0.f;
    for (int c = tid; c < CD; c += 256) s += p[c];
    float m = blockReduce(s, false) * (1.f / CD);
    float ss = 0.f;
    for (int c = tid; c < CD; c += 256) {
        float uu = p[c] - m;
        g_u[(size_t)n * CD + c] = uu;
        ss += uu * uu;
    }
    float su = blockReduce(ss, false) * (1.f / CD);
    if (tid == 0) g_su2[n] = su;
}

__global__ __launch_bounds__(256) void tdot_kernel()
{
    int row = blockIdx.x, b = row >> 4, tid = threadIdx.x;
    float s = 0.f;
    for (int c = tid; c < CD; c += 256)
        s += g_rdq[(size_t)row * CD + c] * g_v[b * CD + c];
    s = blockReduce(s, false);
    if (tid == 0) g_t[row] = s;
}

__global__ __launch_bounds__(256) void dsoftmax_kernel()
{
    int row = blockIdx.x, b = row >> 4, tid = threadIdx.x;
    float lg[8], sv[8];
    float tval = g_t[row];
    float mvb = g_mv2[b];
    float mx = -1e30f;
#pragma unroll
    for (int i = 0; i < 8; i++) {
        int n = tid + i * 256;
        float s2 = g_su2[n] - (2.f / CD) * g_uv[b * NPROT + n] + mvb + 1e-5f;
        float s = sqrtf(fmaxf(s2, 1e-20f));
        sv[i] = s;
        float v = SCALE_C * (g_M[(size_t)row * NPROT + n] - tval) / s;
        lg[i] = v;
        mx = fmaxf(mx, v);
    }
    mx = blockReduce(mx, true);
    float sum = 0.f;
#pragma unroll
    for (int i = 0; i < 8; i++) { float e = expf(lg[i] - mx); lg[i] = e; sum += e; }
    sum = blockReduce(sum, false);
    float inv = 1.f / sum;
    float ws = 0.f;
#pragma unroll
    for (int i = 0; i < 8; i++) {
        float w = lg[i] * inv / sv[i];
        g_M[(size_t)row * NPROT + tid + i * 256] = w;
        ws += w;
    }
    ws = blockReduce(ws, false);
    if (tid == 0) g_sumw[row] = ws;
}

__global__ __launch_bounds__(256)
void fpro_kernel(const float* __restrict__ frel, float* __restrict__ out_fpro)
{
    int row = blockIdx.x, b = row >> 4, q = row & 15, tid = threadIdx.x;
    float sw = g_sumw[row], smw = g_smw[q];
    for (int c = tid; c < CD; c += 256) {
        float val = frel[(size_t)row * CD + c] + g_y[(size_t)row * CD + c]
                  - sw * g_v[b * CD + c];
        g_fpro[(size_t)row * CD + c] = val;
        out_fpro[(size_t)row * CD + c] = val * smw;
    }
}

__global__ __launch_bounds__(256)
void bias3_kernel(const int* __restrict__ cam_ids, const float* __restrict__ cam_table)
{
    int z = blockIdx.x;
    int row = z >> 2, j = z & 3, b = row >> 4, tid = threadIdx.x;
    int inst = g_omap[b * 4 + j];
    int cr = cam_ids[inst] - 1;
    cr = max(0, min(5, cr));
    float s = 0.f;
    for (int c = tid; c < CD; c += 256)
        s += g_qc2[(size_t)row * CD + c] * cam_table[(size_t)cr * CD + c];
    s = blockReduce(s, false);
    if (tid == 0) g_bias3[z] = s;
}

// ----------------------------- launch --------------------------------------
static inline dim3 gt(int M, int N, int Z, int BM) {
    return dim3((N + 63) / 64, (M + BM - 1) / BM, Z);
}

extern "C" void kernel_launch(void* const* d_in, const int* in_sizes, int n_in,
                              void* d_out, int out_size)
{
    // ---- order-agnostic input binding by element count ----
    const float* x = nullptr;
    const float* query_v = nullptr;
    const float* weights = nullptr;
    const float* cam_tab = nullptr;
    const int*   cam_ids = nullptr;
    const unsigned int* sub = nullptr;
    Ptr5 big; int nbig = 0, n32 = 0;
    for (int i = 0; i < n_in; i++) {
        switch (in_sizes[i]) {
            case 18874368: x = (const float*)d_in[i]; break;
            case 32768:    query_v = (const float*)d_in[i]; break;
            case 16:       weights = (const float*)d_in[i]; break;
            case 12288:    cam_tab = (const float*)d_in[i]; break;
            case 589824:   /* pos_embed unused */ break;
            case 4194304:  if (nbig < 5) big.p[nbig++] = (const float*)d_in[i]; break;
            case 32:
                if (n32 == 0) cam_ids = (const int*)d_in[i];
                else          sub     = (const unsigned int*)d_in[i];
                n32++;
                break;
            default: break;
        }
    }

    // ---- DEVICE addresses for every scratch symbol passed as kernel arg ----
    float *xs, *S, *g2, *rq1, *qc1, *lg1, *qln, *v, *u, *uv;
    float *tmp512, *rdq, *M, *y, *fpro, *qc2, *lg2, *lg3, *wb;
    cudaGetSymbolAddress((void**)&xs,    g_xs);
    cudaGetSymbolAddress((void**)&S,     g_S);
    cudaGetSymbolAddress((void**)&g2,    g_g2);
    cudaGetSymbolAddress((void**)&rq1,   g_rq1);
    cudaGetSymbolAddress((void**)&qc1,   g_qc1);
    cudaGetSymbolAddress((void**)&lg1,   g_lg1);
    cudaGetSymbolAddress((void**)&qln,   g_qln);
    cudaGetSymbolAddress((void**)&v,     g_v);
    cudaGetSymbolAddress((void**)&u,     g_u);
    cudaGetSymbolAddress((void**)&uv,    g_uv);
    cudaGetSymbolAddress((void**)&tmp512,g_tmp512);
    cudaGetSymbolAddress((void**)&rdq,   g_rdq);
    cudaGetSymbolAddress((void**)&M,     g_M);
    cudaGetSymbolAddress((void**)&y,     g_y);
    cudaGetSymbolAddress((void**)&fpro,  g_fpro);
    cudaGetSymbolAddress((void**)&qc2,   g_qc2);
    cudaGetSymbolAddress((void**)&lg2,   g_lg2);
    cudaGetSymbolAddress((void**)&lg3,   g_lg3);
    cudaGetSymbolAddress((void**)&wb,    g_wbuf);
    const float* Wcq  = wb;
    const float* Wcg  = wb + WSZ;
    const float* Wdq  = wb + 2 * WSZ;
    const float* Wdg  = wb + 3 * WSZ;
    const float* proto = wb + 4 * WSZ;

    float* out = (float*)d_out;
    float* f_rel = out;
    float* f_pro = out + OFS;
    float* f_rec = out + 2 * OFS;
    float* f_cor = out + 3 * OFS;

    // ---- classify the five 4M tensors, route into fixed slots ----
    classify_zero<<<1, 32>>>();
    classify_sum<<<dim3(256, 5), 256>>>(big);
    classify_pick<<<1, 32>>>();
    router_copy<<<dim3(512, 5), 256>>>(big);

    setup_kernel<<<1, 128>>>(sub, weights);
    transpose_kernel<<<dim3(64, 9, 32), dim3(32, 8)>>>(x);
    colnorm_kernel<<<BATCH * PT, 256>>>();

    // gram S[p,q] = xs[p]·xs[q]   (NT, 288x288xK2048, z=32)
    gemm_t<0,64><<<gt(PT, PT, BATCH, 64), 256>>>(xs, CD, (long long)PT * CD,
        xs, CD, (long long)PT * CD, S, PT, (long long)PT * PT,
        PT, PT, CD, 0, 0, 0);
    softmaxS_kernel<<<BATCH * PT, 256>>>();
    // g2 = S @ xs   (NN, 288x2048xK288)
    gemm_t<1,64><<<gt(PT, CD, BATCH, 64), 256>>>(S, PT, (long long)PT * PT,
        xs, CD, (long long)PT * CD, g2, CD, (long long)PT * CD,
        PT, CD, PT, 0, 0, 0);

    // rq1 = query @ Wcq^T ; qc1 = rq1 @ Wcg
    gemm_t<0,16><<<gt(QN, CD, 1, 16), 256>>>(query_v, CD, 0, Wcq, CD, 0,
        rq1, CD, 0, QN, CD, CD, 0, 0, 0);
    gemm_t<1,16><<<gt(QN, CD, 1, 16), 256>>>(rq1, CD, 0, Wcg, CD, 0,
        qc1, CD, 0, QN, CD, CD, 0, 0, 0);
    // lg1[b,q,n] = qc1[q]·g2[b,n]
    gemm_t<0,16><<<gt(QN, PT, BATCH, 16), 256>>>(qc1, CD, 0,
        g2, CD, (long long)PT * CD, lg1, PT, (long long)QN * PT,
        QN, PT, CD, 0, 0, 0);
    catcher_softmax_kernel<<<512, 256>>>(lg1, PT, 0);
    // f_rel = att1 @ g2
    gemm_t<1,16><<<gt(QN, CD, BATCH, 16), 256>>>(lg1, PT, (long long)QN * PT,
        g2, CD, (long long)PT * CD, f_rel, CD, (long long)QN * CD,
        QN, CD, PT, 0, 0, 0);

    // ---- deltaor (LN factorized) ----
    stats1_kernel<<<BATCH, 256>>>(f_rel);
    ln_kernel<<<512, 256>>>(f_rel);
    protoprep_kernel<<<NPROT, 256>>>(proto);
    gemm_t<0,64><<<gt(512, CD, 1, 64), 256>>>(qln, CD, 0, Wdq, CD, 0,
        tmp512, CD, 0, 512, CD, CD, 0, 0, 0);
    gemm_t<1,64><<<gt(512, CD, 1, 64), 256>>>(tmp512, CD, 0, Wdg, CD, 0,
        rdq, CD, 0, 512, CD, CD, 0, 0, 0);
    gemm_t<0,16><<<gt(BATCH, NPROT, 1, 16), 256>>>(v, CD, 0, u, CD, 0,
        uv, NPROT, 0, BATCH, NPROT, CD, 0, 0, 0);
    gemm_t<0,64><<<gt(512, NPROT, 1, 64), 256>>>(rdq, CD, 0, u, CD, 0,
        M, NPROT, 0, 512, NPROT, CD, 0, 0, 0);
    tdot_kernel<<<512, 256>>>();
    dsoftmax_kernel<<<512, 256>>>();
    gemm_t<1,64><<<gt(512, CD, 1, 64), 256>>>(M, NPROT, 0, u, CD, 0,
        y, CD, 0, 512, CD, NPROT, 0, 0, 0);
    fpro_kernel<<<512, 256>>>(f_rel, f_pro);

    // ---- shared projection of raw f_pro ----
    gemm_t<0,64><<<gt(512, CD, 1, 64), 256>>>(fpro, CD, 0, Wcq, CD, 0,
        tmp512, CD, 0, 512, CD, CD, 0, 0, 0);
    gemm_t<1,64><<<gt(512, CD, 1, 64), 256>>>(tmp512, CD, 0, Wcg, CD, 0,
        qc2, CD, 0, 512, CD, CD, 0, 0, 0);

    // f_rec
    gemm_t<0,16><<<gt(QN, PT, BATCH, 16), 256>>>(qc2, CD, (long long)QN * CD,
        g2, CD, (long long)PT * CD, lg2, PT, (long long)QN * PT,
        QN, PT, CD, 0, 0, 0);
    catcher_softmax_kernel<<<512, 256>>>(lg2, PT, 0);
    gemm_t<1,16><<<gt(QN, CD, BATCH, 16), 256>>>(lg2, PT, (long long)QN * PT,
        g2, CD, (long long)PT * CD, f_rec, CD, (long long)QN * CD,
        QN, CD, PT, 0, 0, 0);

    // f_cor: 128 gathered blocks (offset tables), per-block cam bias
    gemm_t<0,16><<<gt(QN, PT, 128, 16), 256>>>(qc2, CD, 0,
        g2, CD, 0, lg3, 4 * PT, 0, QN, PT, CD, 0, 1, 0);
    bias3_kernel<<<2048, 256>>>(cam_ids, cam_tab);
    catcher_softmax_kernel<<<512, 256>>>(lg3, 4 * PT, 1);
    for (int j = 0; j < 4; j++) {
        gemm_t<1,16><<<gt(QN, CD, BATCH, 16), 256>>>(lg3, 4 * PT, 0,
            g2, CD, 0, f_cor, CD, (long long)QN * CD,
            QN, CD, PT, (j > 0) ? 1 : 0, 2, j * 32);
    }
}